// round 3
// baseline (speedup 1.0000x reference)
#include <cuda_runtime.h>

#define B_WIN 2048
#define NTOK  98
#define NHEAD 4
#define HD    32
#define C3    384
#define DIMM  128
#define NWIN  64
#define NPAD  100   // padded row stride for attn smem (float4-aligned)
#define NN    (NTOK * NTOK)   // 9604
#define RPB_ROWS 507

// Scratch (device globals: allocation-free rule)
__device__ float g_bm[(size_t)NWIN * NHEAD * NN];              // bias + mask, 9.8 MB
__device__ float g_tmp[(size_t)B_WIN * NTOK * DIMM];           // per-head attention output, 103 MB

// ---------------------------------------------------------------------------
// Kernel A: fold rpb gather + window mask into one table:
//   g_bm[w][h][q*98+k] = rpb_table[rpi[q,k]][h] + mask[w][q][k]
// NOTE: rpi is int32 on the wire (JAX default x64-disabled downcasts int64).
// ---------------------------------------------------------------------------
__global__ void bm_kernel(const int* __restrict__ rpi,
                          const float* __restrict__ table,
                          const float* __restrict__ mask) {
    int i = blockIdx.x * blockDim.x + threadIdx.x;
    if (i >= NWIN * NN) return;
    int w = i / NN;
    int e = i - w * NN;
    int r = rpi[e];
    r = (r < 0) ? 0 : (r >= RPB_ROWS ? RPB_ROWS - 1 : r);   // defensive clamp
    float mk = mask[(size_t)w * NN + e];
#pragma unroll
    for (int h = 0; h < NHEAD; h++) {
        g_bm[((size_t)w * NHEAD + h) * NN + e] = table[r * NHEAD + h] + mk;
    }
}

// ---------------------------------------------------------------------------
// Kernel B: attention per (window b, head h). 256 threads.
// smem: Qs[100][32] (pre-scaled, 2 zero pad rows), Kt[32][100] (transposed),
//       Vs[98][32], At[98][100]
// ---------------------------------------------------------------------------
__global__ __launch_bounds__(256) void attn_kernel(const float* __restrict__ x) {
    extern __shared__ float sm[];
    float* Qs = sm;               // 100*32 = 3200
    float* Kt = sm + 3200;        // 32*100 = 3200
    float* Vs = sm + 6400;        // 98*32  = 3136
    float* At = sm + 9536;        // 98*100 = 9800

    const int h = blockIdx.x;
    const int b = blockIdx.y;
    const int tid  = threadIdx.x;
    const int lane = tid & 31;
    const int wid  = tid >> 5;

    const float scale = 0.17677669529663687f;  // 1/sqrt(32)
    const float* xb = x + (size_t)b * NTOK * C3;

    // ---- load Q (scaled), K (transposed), V ----
    for (int i = tid; i < NTOK * HD; i += 256) {
        int q = i >> 5, d = i & 31;
        Qs[i] = xb[q * C3 + h * HD + d] * scale;
        Kt[d * NPAD + q] = xb[q * C3 + DIMM + h * HD + d];
        Vs[i] = xb[q * C3 + 2 * DIMM + h * HD + d];
    }
    if (tid < 64) Qs[NTOK * HD + tid] = 0.0f;   // zero pad rows 98,99 of Q
    __syncthreads();

    // ---- QK^T + bias + mask -> At ----
    const size_t bmbase = ((size_t)(b & (NWIN - 1)) * NHEAD + h) * NN;
    for (int qg = wid; qg < 25; qg += 8) {
        int q0 = qg * 4;
        int nq = (q0 + 4 <= NTOK) ? 4 : (NTOK - q0);   // 4 or 2
        float acc[4][4];
#pragma unroll
        for (int j = 0; j < 4; j++)
#pragma unroll
            for (int s = 0; s < 4; s++) acc[j][s] = 0.0f;

#pragma unroll 4
        for (int d = 0; d < HD; d++) {
            float k0v = Kt[d * NPAD + lane];
            float k1v = Kt[d * NPAD + lane + 32];
            float k2v = Kt[d * NPAD + lane + 64];
            float k3v = (lane < 2) ? Kt[d * NPAD + lane + 96] : 0.0f;
#pragma unroll
            for (int j = 0; j < 4; j++) {
                float qv = Qs[(q0 + j) * HD + d];
                acc[j][0] = fmaf(qv, k0v, acc[j][0]);
                acc[j][1] = fmaf(qv, k1v, acc[j][1]);
                acc[j][2] = fmaf(qv, k2v, acc[j][2]);
                acc[j][3] = fmaf(qv, k3v, acc[j][3]);
            }
        }
#pragma unroll
        for (int j = 0; j < 4; j++) {
            if (j >= nq) break;
            int q = q0 + j;
            const float* bm = &g_bm[bmbase + (size_t)q * NTOK];
            At[q * NPAD + lane]      = acc[j][0] + __ldg(bm + lane);
            At[q * NPAD + lane + 32] = acc[j][1] + __ldg(bm + lane + 32);
            At[q * NPAD + lane + 64] = acc[j][2] + __ldg(bm + lane + 64);
            if (lane < 2)
                At[q * NPAD + lane + 96] = acc[j][3] + __ldg(bm + lane + 96);
        }
    }
    __syncthreads();

    // ---- softmax per row (warp per row) ----
    for (int q = wid; q < NTOK; q += 8) {
        float* row = &At[q * NPAD];
        float v0 = row[lane];
        float v1 = row[lane + 32];
        float v2 = row[lane + 64];
        float v3 = (lane < 2) ? row[lane + 96] : -3.0e38f;
        float m = fmaxf(fmaxf(v0, v1), fmaxf(v2, v3));
#pragma unroll
        for (int off = 16; off > 0; off >>= 1)
            m = fmaxf(m, __shfl_xor_sync(0xffffffffu, m, off));
        float e0 = __expf(v0 - m);
        float e1 = __expf(v1 - m);
        float e2 = __expf(v2 - m);
        float e3 = (lane < 2) ? __expf(v3 - m) : 0.0f;
        float s = e0 + e1 + e2 + e3;
#pragma unroll
        for (int off = 16; off > 0; off >>= 1)
            s += __shfl_xor_sync(0xffffffffu, s, off);
        float inv = __frcp_rn(s);
        row[lane]      = e0 * inv;
        row[lane + 32] = e1 * inv;
        row[lane + 64] = e2 * inv;
        if (lane < 2) row[lane + 96] = e3 * inv;
    }
    __syncthreads();

    // ---- PV: out[q][d] = sum_k At[q][k] * Vs[k][d]; lane owns d = lane ----
    {
        float acc[13];
#pragma unroll
        for (int j = 0; j < 13; j++) acc[j] = 0.0f;

        for (int k0 = 0; k0 < 96; k0 += 8) {
            float vk[8];
#pragma unroll
            for (int i = 0; i < 8; i++) vk[i] = Vs[(k0 + i) * HD + lane];
#pragma unroll
            for (int j = 0; j < 13; j++) {
                int q = wid + 8 * j;
                if (q < NTOK) {
                    const float* ar = &At[q * NPAD + k0];
                    float4 a = *(const float4*)ar;
                    float4 c = *(const float4*)(ar + 4);
                    float t = acc[j];
                    t = fmaf(a.x, vk[0], t);
                    t = fmaf(a.y, vk[1], t);
                    t = fmaf(a.z, vk[2], t);
                    t = fmaf(a.w, vk[3], t);
                    t = fmaf(c.x, vk[4], t);
                    t = fmaf(c.y, vk[5], t);
                    t = fmaf(c.z, vk[6], t);
                    t = fmaf(c.w, vk[7], t);
                    acc[j] = t;
                }
            }
        }
        // tail k = 96, 97
        {
            float v0 = Vs[96 * HD + lane];
            float v1 = Vs[97 * HD + lane];
#pragma unroll
            for (int j = 0; j < 13; j++) {
                int q = wid + 8 * j;
                if (q < NTOK) {
                    acc[j] = fmaf(At[q * NPAD + 96], v0, acc[j]);
                    acc[j] = fmaf(At[q * NPAD + 97], v1, acc[j]);
                }
            }
        }
#pragma unroll
        for (int j = 0; j < 13; j++) {
            int q = wid + 8 * j;
            if (q < NTOK)
                g_tmp[((size_t)b * NTOK + q) * DIMM + h * HD + lane] = acc[j];
        }
    }
}

// ---------------------------------------------------------------------------
// Kernel C: projection  out[r][c] = sum_d g_tmp[r][d] * W[c][d] + b[c]
// ---------------------------------------------------------------------------
__global__ __launch_bounds__(256) void proj_kernel(const float* __restrict__ pw,
                                                   const float* __restrict__ pb,
                                                   float* __restrict__ out) {
    extern __shared__ float sm[];
    float* Ws = sm;                 // [128][129] : Ws[d*129+c] = W[c][d]
    float* Is = sm + 128 * 129;     // [32][128]

    const int tid = threadIdx.x;
    const size_t row0 = (size_t)blockIdx.x * 32;

    for (int i = tid; i < DIMM * DIMM; i += 256) {
        int c = i >> 7, d = i & 127;
        Ws[d * 129 + c] = pw[i];            // coalesced read, conflict-free scatter
    }
    for (int i = tid; i < 32 * DIMM; i += 256)
        Is[i] = g_tmp[row0 * DIMM + i];
    __syncthreads();

    const int c  = tid & 127;
    const int rh = tid >> 7;      // 0 or 1 -> rows rh*16 .. rh*16+15
    float acc[16];
#pragma unroll
    for (int j = 0; j < 16; j++) acc[j] = 0.0f;

    for (int d0 = 0; d0 < DIMM; d0 += 8) {
        float w[8];
#pragma unroll
        for (int i = 0; i < 8; i++) w[i] = Ws[(d0 + i) * 129 + c];
#pragma unroll
        for (int j = 0; j < 16; j++) {
            const float* ir = &Is[(rh * 16 + j) * DIMM + d0];
            float4 a = *(const float4*)ir;
            float4 b2 = *(const float4*)(ir + 4);
            float t = acc[j];
            t = fmaf(a.x, w[0], t);
            t = fmaf(a.y, w[1], t);
            t = fmaf(a.z, w[2], t);
            t = fmaf(a.w, w[3], t);
            t = fmaf(b2.x, w[4], t);
            t = fmaf(b2.y, w[5], t);
            t = fmaf(b2.z, w[6], t);
            t = fmaf(b2.w, w[7], t);
            acc[j] = t;
        }
    }
    float bias = pb[c];
#pragma unroll
    for (int j = 0; j < 16; j++)
        out[(row0 + rh * 16 + j) * DIMM + c] = acc[j] + bias;
}

// ---------------------------------------------------------------------------
extern "C" void kernel_launch(void* const* d_in, const int* in_sizes, int n_in,
                              void* d_out, int out_size) {
    const float* x     = (const float*)d_in[0];
    const int*   rpi   = (const int*)d_in[1];      // int32 on the wire
    const float* mask  = (const float*)d_in[2];
    const float* table = (const float*)d_in[3];
    const float* pw    = (const float*)d_in[4];
    const float* pb    = (const float*)d_in[5];
    float*       out   = (float*)d_out;

    const int smem_attn = (3200 + 3200 + 3136 + 9800) * 4;   // 77344 B
    const int smem_proj = (128 * 129 + 32 * 128) * 4;        // 82432 B
    cudaFuncSetAttribute(attn_kernel, cudaFuncAttributeMaxDynamicSharedMemorySize, smem_attn);
    cudaFuncSetAttribute(proj_kernel, cudaFuncAttributeMaxDynamicSharedMemorySize, smem_proj);

    bm_kernel<<<(NWIN * NN + 255) / 256, 256>>>(rpi, table, mask);
    attn_kernel<<<dim3(NHEAD, B_WIN), 256, smem_attn>>>(x);
    proj_kernel<<<(B_WIN * NTOK) / 32, 256, smem_proj>>>(pw, pb, out);
}